// round 1
// baseline (speedup 1.0000x reference)
#include <cuda_runtime.h>
#include <cstdint>

// ---------------------------------------------------------------------------
// TopKRouter: logits = x @ gate_w^T  (16384 x 2048 x 64, fp32)
//             softmax, top-2 (normalized), load-balance aux loss.
// Output layout (fp32): [top_indices (BS*2)] [top_weights (BS*2)] [aux ...fill]
// ---------------------------------------------------------------------------

#define NEXP 64
#define DIM  2048
#define KC   32           // K-chunk
#define TM   128          // tokens per block
#define NCH  (DIM / KC)   // 64 chunks
#define MAXBLK 256

// Deterministic reduction scratch (per-block slots, summed in fixed order).
__device__ float g_Pblk[MAXBLK * NEXP];
__device__ float g_zblk[MAXBLK];
__device__ int   g_cnt_i[NEXP];

__global__ void zero_scratch_k() {
    int i = threadIdx.x;
    if (i < NEXP) g_cnt_i[i] = 0;
}

__device__ __forceinline__ unsigned smem_u32(const void* p) {
    return (unsigned)__cvta_generic_to_shared(p);
}
__device__ __forceinline__ void cp16(unsigned s, const float* g) {
    asm volatile("cp.async.cg.shared.global [%0], [%1], 16;" :: "r"(s), "l"(g));
}
__device__ __forceinline__ void cp_commit() {
    asm volatile("cp.async.commit_group;");
}

// Packed fp32x2 FMA (sm_100+ PTX; ptxas never auto-fuses this).
#define FMA2(d, a, b) \
    asm("fma.rn.f32x2 %0, %1, %2, %0;" : "+l"(d) : "l"(a), "l"(b))

__global__ void __launch_bounds__(256, 1)
router_kernel(const float* __restrict__ X, const float* __restrict__ W,
              float* __restrict__ out, int BS)
{
    extern __shared__ float smem[];
    float* xs = smem;                 // [2][TM][KC]  = 8192 floats (32 KB)
    float* ws = smem + 2 * TM * KC;   // [2][NEXP][KC]= 4096 floats (16 KB)

    const int tid = threadIdx.x;
    const int tx = tid & 15;          // expert group: experts tx*4 .. tx*4+3
    const int ty = tid >> 4;          // token  group: tokens  ty*8 .. ty*8+7
    const int tok0 = blockIdx.x * TM;

    const int lrow = tid >> 3;        // 0..31   (loader row)
    const int lc4  = (tid & 7) * 4;   // 0,4,..28 (loader float4 col)

    // ---- prologue: chunk 0 -> stage 0 ----
    {
        const float* xg = X + (size_t)tok0 * DIM + lc4;
        #pragma unroll
        for (int r = 0; r < 4; r++)
            cp16(smem_u32(xs + (lrow + 32 * r) * KC + lc4),
                 xg + (size_t)(lrow + 32 * r) * DIM);
        const float* wg = W + lc4;
        #pragma unroll
        for (int r = 0; r < 2; r++)
            cp16(smem_u32(ws + (lrow + 32 * r) * KC + lc4),
                 wg + (size_t)(lrow + 32 * r) * DIM);
        cp_commit();
    }

    // Accumulators: packed over K (lo = even-k partial, hi = odd-k partial).
    unsigned long long acc[8][4];
    #pragma unroll
    for (int i = 0; i < 8; i++)
        #pragma unroll
        for (int j = 0; j < 4; j++) acc[i][j] = 0ull;

    for (int c = 0; c < NCH; c++) {
        const int cur = c & 1;
        if (c + 1 < NCH) {
            const int nxt = cur ^ 1;
            const int k0 = (c + 1) * KC;
            const float* xg = X + (size_t)tok0 * DIM + k0 + lc4;
            float* xsd = xs + nxt * TM * KC;
            #pragma unroll
            for (int r = 0; r < 4; r++)
                cp16(smem_u32(xsd + (lrow + 32 * r) * KC + lc4),
                     xg + (size_t)(lrow + 32 * r) * DIM);
            const float* wg = W + k0 + lc4;
            float* wsd = ws + nxt * NEXP * KC;
            #pragma unroll
            for (int r = 0; r < 2; r++)
                cp16(smem_u32(wsd + (lrow + 32 * r) * KC + lc4),
                     wg + (size_t)(lrow + 32 * r) * DIM);
            cp_commit();
            asm volatile("cp.async.wait_group 1;");
        } else {
            asm volatile("cp.async.wait_group 0;");
        }
        __syncthreads();

        const float* xr = xs + cur * TM * KC  + (ty * 8) * KC;
        const float* wr = ws + cur * NEXP * KC + (tx * 4) * KC;

        #pragma unroll
        for (int q = 0; q < 8; q++) {
            // Skewed quad order per tx-lane: spreads smem bank-quads so the
            // 16-distinct-row w reads are conflict-free (no XOR swizzle).
            const int kq = ((q + tx) & 7) * 4;
            ulonglong2 wv0 = *reinterpret_cast<const ulonglong2*>(wr + 0 * KC + kq);
            ulonglong2 wv1 = *reinterpret_cast<const ulonglong2*>(wr + 1 * KC + kq);
            ulonglong2 wv2 = *reinterpret_cast<const ulonglong2*>(wr + 2 * KC + kq);
            ulonglong2 wv3 = *reinterpret_cast<const ulonglong2*>(wr + 3 * KC + kq);
            #pragma unroll
            for (int i = 0; i < 8; i++) {
                ulonglong2 xv = *reinterpret_cast<const ulonglong2*>(xr + i * KC + kq);
                FMA2(acc[i][0], xv.x, wv0.x);  FMA2(acc[i][0], xv.y, wv0.y);
                FMA2(acc[i][1], xv.x, wv1.x);  FMA2(acc[i][1], xv.y, wv1.y);
                FMA2(acc[i][2], xv.x, wv2.x);  FMA2(acc[i][2], xv.y, wv2.y);
                FMA2(acc[i][3], xv.x, wv3.x);  FMA2(acc[i][3], xv.y, wv3.y);
            }
        }
        __syncthreads();
    }

    // ---- epilogue: logits tile -> smem overlay (stride 68 to spread banks)
    float* lg = smem;                     // [TM][68] = 8704 floats (34 KB)
    #pragma unroll
    for (int i = 0; i < 8; i++)
        #pragma unroll
        for (int j = 0; j < 4; j++) {
            float2 v = *reinterpret_cast<float2*>(&acc[i][j]);
            lg[(ty * 8 + i) * 68 + (tx * 4 + j)] = v.x + v.y;
        }

    float* sm_m  = smem + 8704;           // [TM] row max
    float* sm_iv = smem + 8704 + 128;     // [TM] 1/sum
    int*   scnt  = (int*)(smem + 8704 + 256);  // [NEXP]
    float* sz    = smem + 8704 + 320;     // [1]
    if (tid < NEXP) scnt[tid] = 0;
    if (tid == 0) *sz = 0.f;
    __syncthreads();

    if (tid < TM) {
        const float* row = lg + tid * 68;
        float m = row[0]; int i1 = 0;
        for (int e = 1; e < NEXP; e++) {
            float v = row[e];
            if (v > m) { m = v; i1 = e; }      // strict > : lowest index on tie
        }
        float sum = 0.f;
        for (int e = 0; e < NEXP; e++) sum += __expf(row[e] - m);
        float m2 = -3.4e38f; int i2 = 0;
        for (int e = 0; e < NEXP; e++) {
            if (e == i1) continue;
            float v = row[e];
            if (v > m2) { m2 = v; i2 = e; }
        }
        // normalized top-2 weights: e1 = exp(0) = 1
        float e2 = __expf(m2 - m);
        float r1 = 1.f / (1.f + e2);
        float r2 = e2 * r1;

        const int tg = tok0 + tid;
        out[2 * tg + 0] = (float)i1;
        out[2 * tg + 1] = (float)i2;
        out[(size_t)2 * BS + 2 * tg + 0] = r1;
        out[(size_t)2 * BS + 2 * tg + 1] = r2;

        sm_m[tid]  = m;
        sm_iv[tid] = 1.f / sum;
        float lse = m + __logf(sum);
        atomicAdd(sz, lse * lse);
        atomicAdd(&scnt[i1], 1);
        atomicAdd(&scnt[i2], 1);
    }
    __syncthreads();

    if (tid < NEXP) {
        float p = 0.f;
        for (int t = 0; t < TM; t++)
            p += __expf(lg[t * 68 + tid] - sm_m[t]) * sm_iv[t];
        g_Pblk[blockIdx.x * NEXP + tid] = p;           // per-block slot: deterministic
        atomicAdd(&g_cnt_i[tid], scnt[tid]);           // int atomics: deterministic
    }
    if (tid == 0) g_zblk[blockIdx.x] = *sz;
}

__global__ void finalize_k(float* __restrict__ out, int BS, int out_size, int nblk) {
    __shared__ float sP[NEXP];
    const int e = threadIdx.x;
    if (e < NEXP) {
        float p = 0.f;
        for (int b = 0; b < nblk; b++) p += g_Pblk[b * NEXP + e];
        sP[e] = p;
    }
    __syncthreads();
    if (e == 0) {
        float z = 0.f;
        for (int b = 0; b < nblk; b++) z += g_zblk[b];
        const float invBSK = 1.f / (2.f * (float)BS);
        const float invBS  = 1.f / (float)BS;
        float bal = 0.f;
        for (int k = 0; k < NEXP; k++)
            bal += ((float)g_cnt_i[k] * invBSK) * (sP[k] * invBS);
        bal *= (float)NEXP;
        float aux = 0.01f * bal + 0.001f * (z * invBS);
        for (int i = 4 * BS; i < out_size; i++) out[i] = aux;
    }
}

extern "C" void kernel_launch(void* const* d_in, const int* in_sizes, int n_in,
                              void* d_out, int out_size)
{
    const float* x = (const float*)d_in[0];
    const float* w = (const float*)d_in[1];
    float* out = (float*)d_out;

    const int Dv = in_sizes[1] / NEXP;   // 2048
    const int BS = in_sizes[0] / Dv;     // 16384 tokens
    const int nblk = BS / TM;            // 128 blocks

    zero_scratch_k<<<1, 64>>>();
    // 48 KB dynamic smem == default limit, no opt-in attribute needed.
    router_kernel<<<nblk, 256, 2 * (TM + NEXP) * KC * (int)sizeof(float)>>>(x, w, out, BS);
    finalize_k<<<1, 64>>>(out, BS, out_size, nblk);
}